// round 14
// baseline (speedup 1.0000x reference)
#include <cuda_runtime.h>
#include <cstdint>

#define Bb 16
#define Nn 64
#define Hh 256
#define Tt 5
#define ROWS (Bb*Nn*Nn)      // 65536 (b,i,j) rows
#define BNH  (Bb*Nn*Hh)      // 262144

typedef unsigned long long ull;

// ---- device scratch ----
__device__ float g_prop [BNH];
__device__ float g_msg  [Tt*BNH];
__device__ float g_Wc   [Hh*Hh];
__device__ float g_fi2v [Bb*Hh];
__device__ float g_fsslv[Bb*Hh];
__device__ float g_biasb[Bb*Hh];
__device__ int   g_rows [ROWS];
__device__ unsigned g_maskb[ROWS/32];   // 2048 words
__device__ int   g_count;
__device__ int   g_bar[Bb];

// ---- packed f32x2 helpers ----
__device__ __forceinline__ ull pack2(float lo, float hi) {
    ull r; asm("mov.b64 %0, {%1,%2};" : "=l"(r) : "f"(lo), "f"(hi)); return r;
}
__device__ __forceinline__ void fma2(ull& d, ull a, ull b) {
    asm("fma.rn.f32x2 %0, %1, %2, %0;" : "+l"(d) : "l"(a), "l"(b));
}
__device__ __forceinline__ void unpack2(ull v, float& lo, float& hi) {
    asm("mov.b64 {%0,%1}, %2;" : "=f"(lo), "=f"(hi) : "l"(v));
}

// ---- cp.async helpers ----
__device__ __forceinline__ uint32_t sptr(const void* p) {
    return (uint32_t)__cvta_generic_to_shared(p);
}
__device__ __forceinline__ void cpa16(uint32_t dst, const void* src, int szbytes) {
    asm volatile("cp.async.ca.shared.global [%0], [%1], 16, %2;"
                 :: "r"(dst), "l"(src), "r"(szbytes));
}
__device__ __forceinline__ void cpa16cg(uint32_t dst, const void* src) {
    asm volatile("cp.async.cg.shared.global [%0], [%1], 16;"
                 :: "r"(dst), "l"(src));
}
#define CP_COMMIT() asm volatile("cp.async.commit_group;")
template<int N> __device__ __forceinline__ void cp_wait() {
    asm volatile("cp.async.wait_group %0;" :: "n"(N));
}

// ============================================================
// Device GEMM body [validated]
// ============================================================
__device__ void dev_gemm(
    const float* __restrict__ A, const float* __restrict__ W,
    const float* __restrict__ bias, float* __restrict__ C,
    int M, int K, int m0, int n0)
{
    __shared__ __align__(16) float AS[2][32][36];
    __shared__ __align__(16) float BS[2][32][64];
    int tid = threadIdx.x;

    int ar = tid >> 3, ac = tid & 7;
    int bk0 = tid >> 4, bc0 = tid & 15;

    auto issue = [&](int s, int k0) {
        bool aok = (m0 + ar) < M;
        const float* asrc = A + (size_t)(aok ? (m0 + ar) : 0) * K + k0 + ac*4;
        cpa16(sptr(&AS[s][ar][ac*4]), asrc, aok ? 16 : 0);
        #pragma unroll
        for (int q = 0; q < 2; q++) {
            int kk = bk0 + q*16;
            cpa16(sptr(&BS[s][kk][bc0*4]), W + (size_t)(k0+kk)*256 + n0 + bc0*4, 16);
        }
        CP_COMMIT();
    };

    int tx = tid & 15, ty = tid >> 4;
    ull acc[2][2] = {};

    issue(0, 0);
    int nt = K >> 5;
    for (int t = 0; t < nt; t++) {
        if (t + 1 < nt) { issue((t+1)&1, (t+1)*32); cp_wait<1>(); }
        else            { cp_wait<0>(); }
        __syncthreads();
        int s = t & 1;
        #pragma unroll
        for (int k = 0; k < 32; k++) {
            float a0 = AS[s][ty*2+0][k];
            float a1 = AS[s][ty*2+1][k];
            float4 b = *(float4*)&BS[s][k][tx*4];
            ull bp0 = pack2(b.x, b.y), bp1 = pack2(b.z, b.w);
            ull aa0 = pack2(a0, a0),   aa1 = pack2(a1, a1);
            fma2(acc[0][0], aa0, bp0); fma2(acc[0][1], aa0, bp1);
            fma2(acc[1][0], aa1, bp0); fma2(acc[1][1], aa1, bp1);
        }
        __syncthreads();
    }

    #pragma unroll
    for (int q = 0; q < 2; q++) {
        int gr = m0 + ty*2 + q;
        if (gr < M) {
            float v[4];
            unpack2(acc[q][0], v[0], v[1]);
            unpack2(acc[q][1], v[2], v[3]);
            #pragma unroll
            for (int c = 0; c < 4; c++) {
                int gc = n0 + tx*4 + c;
                float o = v[c];
                if (bias) o += bias[gc];
                C[(size_t)gr*256 + gc] = o;
            }
        }
    }
}

// ============================================================
// L1: mega0 — Wc || fi2v || fsslv || zero(g_count, g_bar)  [R13 verbatim]
// ============================================================
__global__ __launch_bounds__(256) void mega0_kernel(
    const float* __restrict__ img_fc_w, const float* __restrict__ img_fc_b,
    const float* __restrict__ feat_img_2, const float* __restrict__ feat_img_ssl,
    const float* __restrict__ edge_fc_w1)
{
    int blk = blockIdx.x;
    if (blk == 40) {
        if (threadIdx.x == 0) g_count = 0;
        if (threadIdx.x < Bb) g_bar[threadIdx.x] = 0;
        return;
    }

    const float *A, *W, *bias; float* C; int M, m0, n0;
    if (blk < 32) {
        A = img_fc_w; W = edge_fc_w1 + 256*256; bias = nullptr; C = g_Wc;
        M = 256; m0 = (blk >> 2) * 32; n0 = (blk & 3) * 64;
    } else if (blk < 36) {
        A = feat_img_2; W = img_fc_w; bias = img_fc_b; C = g_fi2v;
        M = Bb; m0 = 0; n0 = (blk - 32) * 64;
    } else {
        A = feat_img_ssl; W = img_fc_w; bias = img_fc_b; C = g_fsslv;
        M = Bb; m0 = 0; n0 = (blk - 36) * 64;
    }
    dev_gemm(A, W, bias, C, M, 256, m0, n0);
}

// ============================================================
// L2: mega1 — compact (256 blocks, full 65536 rows) || biask  [R13 verbatim]
// ============================================================
__global__ __launch_bounds__(256) void mega1_kernel(
    const int* __restrict__ mask, float* __restrict__ out,
    const float* __restrict__ b1, const float* __restrict__ bimg,
    const float* __restrict__ w1)
{
    int blk = blockIdx.x;
    if (blk < 256) {
        int r = blk * 256 + threadIdx.x;
        float4 z = make_float4(0.f, 0.f, 0.f, 0.f);
        float4* o = (float4*)(out + (size_t)r * 8);
        o[0] = z; o[1] = z;
        bool act = (mask[r] != 0);
        unsigned bal = __ballot_sync(0xffffffffu, act);
        if ((threadIdx.x & 31) == 0) g_maskb[r >> 5] = bal;
        if (act) {
            int p = atomicAdd(&g_count, 1);
            g_rows[p] = r;
        }
    } else {
        int b  = (blk - 256) >> 2;
        int ny = (blk - 256) & 3;
        int n = ny*64 + (threadIdx.x & 63);
        int part = threadIdx.x >> 6;
        __shared__ float red[4][64];
        const float* f2 = g_fi2v  + b*256;
        const float* f3 = g_fsslv + b*256;
        float s = 0.f;
        for (int h = part; h < 256; h += 4) {
            s += bimg[h] * __ldg(&w1[(256+h)*256 + n]);
            s += f2[h]   * __ldg(&w1[(512+h)*256 + n]);
            s += f3[h]   * __ldg(&w1[(768+h)*256 + n]);
        }
        red[part][threadIdx.x & 63] = s;
        __syncthreads();
        if (part == 0) {
            int l = threadIdx.x & 63;
            g_biasb[b*256 + n] = b1[n] + red[0][l] + red[1][l] + red[2][l] + red[3][l];
        }
    }
}

// ============================================================
// L3: scan_all — persistent prop0 + 5 scan steps  [R13 verbatim — validated]
// ============================================================
__global__ __launch_bounds__(256) void scan_all_kernel(
    const float* __restrict__ feat_body,
    const float* __restrict__ img_fc_w, const float* __restrict__ img_fc_b,
    const float* __restrict__ node_fc_w, const float* __restrict__ node_fc_b)
{
    __shared__ __align__(16) float AS[2][64][36];
    __shared__ __align__(16) float BS[2][32][36];
    __shared__ float msgT[32][65];
    __shared__ unsigned smask[128];

    int b  = blockIdx.x;
    int n0 = blockIdx.y * 32;
    int tid = threadIdx.x;
    if (tid < 128) smask[tid] = g_maskb[b*128 + tid];
    int tx = tid & 15, ty = tid >> 4;

    for (int phase = 0; phase < 6; phase++) {
        const float* Ab   = (phase == 0) ? (feat_body + (size_t)b*64*256)
                                         : (g_prop    + (size_t)b*64*256);
        const float* W    = (phase == 0) ? img_fc_w
                                         : (node_fc_w + (size_t)(phase-1)*65536);
        const float* bias = (phase == 0) ? img_fc_b
                                         : (node_fc_b + (phase-1)*256);

        auto issue = [&](int s, int k0) {
            #pragma unroll
            for (int p = 0; p < 2; p++) {
                int cid = p*256 + tid; int rr = cid >> 3, cc = cid & 7;
                cpa16cg(sptr(&AS[s][rr][cc*4]), Ab + (size_t)rr*256 + k0 + cc*4);
            }
            int rr2 = tid >> 3, cc2 = tid & 7;
            cpa16(sptr(&BS[s][rr2][cc2*4]), W + (size_t)(k0 + rr2)*256 + n0 + cc2*4, 16);
            CP_COMMIT();
        };

        ull acc[4] = {};
        issue(0, 0);
        for (int kt = 0; kt < 8; kt++) {
            if (kt + 1 < 8) { issue((kt+1)&1, (kt+1)*32); cp_wait<1>(); }
            else            { cp_wait<0>(); }
            __syncthreads();
            int s = kt & 1;
            #pragma unroll
            for (int k = 0; k < 32; k++) {
                float2 bv = *(float2*)&BS[s][k][tx*2];
                ull bp = pack2(bv.x, bv.y);
                #pragma unroll
                for (int q = 0; q < 4; q++) {
                    float a = AS[s][ty*4+q][k];
                    fma2(acc[q], pack2(a, a), bp);
                }
            }
            __syncthreads();
        }

        float b0 = bias[n0 + tx*2], b1 = bias[n0 + tx*2 + 1];
        if (phase == 0) {
            float* pr = g_prop + (size_t)b*64*256;
            #pragma unroll
            for (int q = 0; q < 4; q++) {
                int row = ty*4 + q;
                float v0, v1;
                unpack2(acc[q], v0, v1);
                *(float2*)&pr[(size_t)row*256 + n0 + tx*2] =
                    make_float2(v0 + b0, v1 + b1);
            }
        } else {
            int t = phase - 1;
            float* msgg = g_msg + ((size_t)t*Bb + b) * 64 * 256;
            #pragma unroll
            for (int q = 0; q < 4; q++) {
                int row = ty*4 + q;
                float v0, v1;
                unpack2(acc[q], v0, v1);
                v0 += b0; v1 += b1;
                msgT[tx*2    ][row] = v0;
                msgT[tx*2 + 1][row] = v1;
                *(float2*)&msgg[(size_t)row*256 + n0 + tx*2] = make_float2(v0, v1);
            }
            __syncthreads();

            if (t < Tt - 1) {
                int i = tid >> 2, hg = tid & 3;
                float mi[8], av[8];
                #pragma unroll
                for (int hh = 0; hh < 8; hh++) { mi[hh] = msgT[hg*8+hh][i]; av[hh] = 0.f; }
                unsigned w0 = smask[i*2], w1m = smask[i*2 + 1];
                #pragma unroll 4
                for (int j = 0; j < 32; j++) {
                    if ((w0 >> j) & 1) {
                        #pragma unroll
                        for (int hh = 0; hh < 8; hh++) {
                            float mj = msgT[hg*8+hh][j];
                            av[hh] += fmaxf(mi[hh] + mj, 0.f) * mj;
                        }
                    }
                }
                #pragma unroll 4
                for (int j = 0; j < 32; j++) {
                    if ((w1m >> j) & 1) {
                        #pragma unroll
                        for (int hh = 0; hh < 8; hh++) {
                            float mj = msgT[hg*8+hh][j + 32];
                            av[hh] += fmaxf(mi[hh] + mj, 0.f) * mj;
                        }
                    }
                }
                float* pr = g_prop + ((size_t)b*64 + i)*256 + n0 + hg*8;
                #pragma unroll
                for (int hh = 0; hh < 8; hh++)
                    pr[hh] += fmaxf(mi[hh] + av[hh], 0.f);
            }
        }

        if (phase < 5) {
            __threadfence();
            __syncthreads();
            if (tid == 0) {
                atomicAdd(&g_bar[b], 1);
                while (atomicAdd(&g_bar[b], 0) < 8*(phase+1)) { }
            }
            __syncthreads();
        }
    }
}

// ============================================================
// L4: fuse_v6 — register-staged double-buffered pipeline.
// BM=64, BN=256, BK=16, 256 threads.
// Per iter: issue next-tile LDGs -> regs, run 16-k FMA block on current
// buffer, commit regs -> other buffer, ONE __syncthreads().
// smem: Bs[2][16][264] 33.8K (reused as Hs[32][264]) +
//       As[2][16][72]   9.2K (reused as w2s[2304])  + idx 1K ≈ 45K.
// ============================================================
__global__ __launch_bounds__(256) void fuse_kernel(
    const float* __restrict__ fimg1, const float* __restrict__ w1,
    const float* __restrict__ w2,    const float* __restrict__ b2,
    float* __restrict__ out)
{
    __shared__ __align__(16) float Bs[2][16][264];
    __shared__ __align__(16) float As[2][16][72];
    __shared__ int sRow[64], sB[64], sBI[64], sBJ[64];

    int cnt = g_count;
    int m0  = blockIdx.x * 64;
    if (m0 >= cnt) return;
    int tid = threadIdx.x;

    if (tid < 64) {
        int cl  = min(m0 + tid, cnt - 1);
        int row = g_rows[cl];
        int b = row >> 12, i = (row >> 6) & 63, j = row & 63;
        sRow[tid] = row;
        sB[tid]   = b;
        sBI[tid]  = (b*64 + i) * 256;
        sBJ[tid]  = (b*64 + j) * 256;
    }
    __syncthreads();

    int tx = tid & 31, ty = tid >> 5;
    int bk = tid >> 4, bc = (tid & 15) * 16;   // B staging: row bk, cols bc..bc+15

    ull acc[8][4];
    #pragma unroll
    for (int q = 0; q < 8; q++)
        #pragma unroll
        for (int c = 0; c < 4; c++) acc[q][c] = 0ULL;

    float4 bstage[4];
    float  astage[4];

    auto stage = [&](int k0) {
        const float* Bsrc = (k0 < 256) ? (w1 + (size_t)k0*256)
                                       : (g_Wc + (size_t)(k0-256)*256);
        #pragma unroll
        for (int q = 0; q < 4; q++)
            bstage[q] = __ldg((const float4*)&Bsrc[(size_t)bk*256 + bc + q*4]);
        #pragma unroll
        for (int p = 0; p < 4; p++) {
            int lin = p*256 + tid; int r = lin & 63, kk = lin >> 6;
            int k = k0 + kk;
            float v;
            if (k0 < 256) {
                const float* mi = g_msg + sBI[r] + k;
                const float* mj = g_msg + sBJ[r] + k;
                float m = mi[0] + mj[0];
                #pragma unroll
                for (int t = 1; t < Tt; t++)
                    m = fmaxf(m, mi[(size_t)t*BNH] + mj[(size_t)t*BNH]);
                v = fmaxf(m, 0.f);
            } else {
                v = __ldg(&fimg1[(size_t)sRow[r]*256 + (k - 256)]);
            }
            astage[p] = v;
        }
    };
    auto commit = [&](int s) {
        #pragma unroll
        for (int q = 0; q < 4; q++)
            *(float4*)&Bs[s][bk][bc + q*4] = bstage[q];
        #pragma unroll
        for (int p = 0; p < 4; p++) {
            int lin = p*256 + tid; int r = lin & 63, kk = lin >> 6;
            As[s][kk][r] = astage[p];
        }
    };

    stage(0);
    commit(0);
    __syncthreads();

    for (int st = 0; st < 32; st++) {
        if (st + 1 < 32) stage((st+1)*16);     // LDGs overlap the FMA block
        int s = st & 1;
        #pragma unroll
        for (int k = 0; k < 16; k++) {
            float4 b0 = *(float4*)&Bs[s][k][tx*4];
            float4 b1 = *(float4*)&Bs[s][k][128 + tx*4];
            ull bp0 = pack2(b0.x,b0.y), bp1 = pack2(b0.z,b0.w);
            ull bp2 = pack2(b1.x,b1.y), bp3 = pack2(b1.z,b1.w);
            #pragma unroll
            for (int q = 0; q < 8; q++) {
                float a = As[s][k][ty*8 + q];  // warp-broadcast LDS
                ull aa = pack2(a, a);
                fma2(acc[q][0], aa, bp0); fma2(acc[q][1], aa, bp1);
                fma2(acc[q][2], aa, bp2); fma2(acc[q][3], aa, bp3);
            }
        }
        if (st + 1 < 32) commit((st+1)&1);     // writes the idle buffer
        __syncthreads();
    }

    // A buffers dead: alias as w2s (2304 floats = sizeof(As)).
    float* w2s = &As[0][0][0];
    for (int idx = tid; idx < 2048; idx += 256) {
        int h = idx >> 3, e = idx & 7;
        w2s[h*9 + e] = __ldg(&w2[idx]);
    }

    float (*Hs)[264] = (float(*)[264])&Bs[0][0][0];
    #pragma unroll
    for (int half = 0; half < 2; half++) {
        if ((ty >> 2) == half) {
            int tyl = ty & 3;
            #pragma unroll
            for (int q = 0; q < 8; q++) {
                int rl = tyl*8 + q;
                const float* bb = g_biasb + sB[half*32 + rl]*256;
                float h[8];
                unpack2(acc[q][0], h[0], h[1]);
                unpack2(acc[q][1], h[2], h[3]);
                unpack2(acc[q][2], h[4], h[5]);
                unpack2(acc[q][3], h[6], h[7]);
                #pragma unroll
                for (int c = 0; c < 4; c++) {
                    int col = tx*4 + c;
                    Hs[rl][col] = fmaxf(h[c] + __ldg(&bb[col]), 0.f);
                }
                #pragma unroll
                for (int c = 0; c < 4; c++) {
                    int col = 128 + tx*4 + c;
                    Hs[rl][col] = fmaxf(h[c+4] + __ldg(&bb[col]), 0.f);
                }
            }
        }
        __syncthreads();
        int rl = tid >> 3, e = tid & 7;
        int gidx = m0 + half*32 + rl;
        if (gidx < cnt) {
            float s = 0.f;
            const float* hrow = Hs[rl];
            #pragma unroll 8
            for (int h = 0; h < 256; h++) s += hrow[h] * w2s[h*9 + e];
            out[(size_t)sRow[half*32 + rl]*8 + e] = s + __ldg(&b2[e]);
        }
        __syncthreads();
    }
}

// ============================================================
extern "C" void kernel_launch(void* const* d_in, const int* in_sizes, int n_in,
                              void* d_out, int out_size)
{
    const float* feat_body    = (const float*)d_in[0];
    const float* feat_img_1   = (const float*)d_in[1];
    const float* feat_img_2   = (const float*)d_in[2];
    const float* feat_img_ssl = (const float*)d_in[3];
    const int*   full_mask    = (const int*)  d_in[4];
    const float* img_fc_w     = (const float*)d_in[5];
    const float* img_fc_b     = (const float*)d_in[6];
    const float* node_fc_w    = (const float*)d_in[7];
    const float* node_fc_b    = (const float*)d_in[8];
    const float* edge_fc_w1   = (const float*)d_in[9];
    const float* edge_fc_b1   = (const float*)d_in[10];
    const float* edge_fc_w2   = (const float*)d_in[11];
    const float* edge_fc_b2   = (const float*)d_in[12];
    float* out = (float*)d_out;

    // L1: Wc || fi2v || fsslv || zero(g_count, g_bar)
    mega0_kernel<<<41, 256>>>(img_fc_w, img_fc_b,
                              feat_img_2, feat_img_ssl, edge_fc_w1);
    // L2: compact (full 65536 rows) || biask
    mega1_kernel<<<320, 256>>>(full_mask, out, edge_fc_b1, img_fc_b, edge_fc_w1);
    // L3: persistent scan (prop0 + 5 steps, per-batch barriers)
    scan_all_kernel<<<dim3(Bb, 8), 256>>>(feat_body, img_fc_w, img_fc_b,
                                          node_fc_w, node_fc_b);
    // L4: register-staged double-buffered fuse
    fuse_kernel<<<ROWS/64, 256>>>(feat_img_1, edge_fc_w1, edge_fc_w2,
                                  edge_fc_b2, out);
}

// round 16
// speedup vs baseline: 1.1974x; 1.1974x over previous
#include <cuda_runtime.h>
#include <cstdint>

#define Bb 16
#define Nn 64
#define Hh 256
#define Tt 5
#define ROWS (Bb*Nn*Nn)      // 65536 (b,i,j) rows
#define BNH  (Bb*Nn*Hh)      // 262144

typedef unsigned long long ull;

// ---- device scratch ----
__device__ float g_prop [BNH];
__device__ float g_msg  [Tt*BNH];
__device__ float g_Wc   [Hh*Hh];
__device__ float g_fi2v [Bb*Hh];
__device__ float g_fsslv[Bb*Hh];
__device__ float g_biasb[Bb*Hh];
__device__ int   g_rows [ROWS];
__device__ unsigned g_maskb[ROWS/32];   // 2048 words
__device__ int   g_count;
__device__ int   g_bar[Bb];

// ---- packed f32x2 helpers ----
__device__ __forceinline__ ull pack2(float lo, float hi) {
    ull r; asm("mov.b64 %0, {%1,%2};" : "=l"(r) : "f"(lo), "f"(hi)); return r;
}
__device__ __forceinline__ void fma2(ull& d, ull a, ull b) {
    asm("fma.rn.f32x2 %0, %1, %2, %0;" : "+l"(d) : "l"(a), "l"(b));
}
__device__ __forceinline__ void unpack2(ull v, float& lo, float& hi) {
    asm("mov.b64 {%0,%1}, %2;" : "=f"(lo), "=f"(hi) : "l"(v));
}

// ---- cp.async helpers ----
__device__ __forceinline__ uint32_t sptr(const void* p) {
    return (uint32_t)__cvta_generic_to_shared(p);
}
__device__ __forceinline__ void cpa16(uint32_t dst, const void* src, int szbytes) {
    asm volatile("cp.async.ca.shared.global [%0], [%1], 16, %2;"
                 :: "r"(dst), "l"(src), "r"(szbytes));
}
__device__ __forceinline__ void cpa16cg(uint32_t dst, const void* src) {
    asm volatile("cp.async.cg.shared.global [%0], [%1], 16;"
                 :: "r"(dst), "l"(src));
}
#define CP_COMMIT() asm volatile("cp.async.commit_group;")
template<int N> __device__ __forceinline__ void cp_wait() {
    asm volatile("cp.async.wait_group %0;" :: "n"(N));
}

// ============================================================
// Device GEMM body [validated]
// ============================================================
__device__ void dev_gemm(
    const float* __restrict__ A, const float* __restrict__ W,
    const float* __restrict__ bias, float* __restrict__ C,
    int M, int K, int m0, int n0)
{
    __shared__ __align__(16) float AS[2][32][36];
    __shared__ __align__(16) float BS[2][32][64];
    int tid = threadIdx.x;

    int ar = tid >> 3, ac = tid & 7;
    int bk0 = tid >> 4, bc0 = tid & 15;

    auto issue = [&](int s, int k0) {
        bool aok = (m0 + ar) < M;
        const float* asrc = A + (size_t)(aok ? (m0 + ar) : 0) * K + k0 + ac*4;
        cpa16(sptr(&AS[s][ar][ac*4]), asrc, aok ? 16 : 0);
        #pragma unroll
        for (int q = 0; q < 2; q++) {
            int kk = bk0 + q*16;
            cpa16(sptr(&BS[s][kk][bc0*4]), W + (size_t)(k0+kk)*256 + n0 + bc0*4, 16);
        }
        CP_COMMIT();
    };

    int tx = tid & 15, ty = tid >> 4;
    ull acc[2][2] = {};

    issue(0, 0);
    int nt = K >> 5;
    for (int t = 0; t < nt; t++) {
        if (t + 1 < nt) { issue((t+1)&1, (t+1)*32); cp_wait<1>(); }
        else            { cp_wait<0>(); }
        __syncthreads();
        int s = t & 1;
        #pragma unroll
        for (int k = 0; k < 32; k++) {
            float a0 = AS[s][ty*2+0][k];
            float a1 = AS[s][ty*2+1][k];
            float4 b = *(float4*)&BS[s][k][tx*4];
            ull bp0 = pack2(b.x, b.y), bp1 = pack2(b.z, b.w);
            ull aa0 = pack2(a0, a0),   aa1 = pack2(a1, a1);
            fma2(acc[0][0], aa0, bp0); fma2(acc[0][1], aa0, bp1);
            fma2(acc[1][0], aa1, bp0); fma2(acc[1][1], aa1, bp1);
        }
        __syncthreads();
    }

    #pragma unroll
    for (int q = 0; q < 2; q++) {
        int gr = m0 + ty*2 + q;
        if (gr < M) {
            float v[4];
            unpack2(acc[q][0], v[0], v[1]);
            unpack2(acc[q][1], v[2], v[3]);
            #pragma unroll
            for (int c = 0; c < 4; c++) {
                int gc = n0 + tx*4 + c;
                float o = v[c];
                if (bias) o += bias[gc];
                C[(size_t)gr*256 + gc] = o;
            }
        }
    }
}

// ============================================================
// L1: mega0 — Wc || fi2v || fsslv || zero(g_count, g_bar)  [R13 verbatim]
// ============================================================
__global__ __launch_bounds__(256) void mega0_kernel(
    const float* __restrict__ img_fc_w, const float* __restrict__ img_fc_b,
    const float* __restrict__ feat_img_2, const float* __restrict__ feat_img_ssl,
    const float* __restrict__ edge_fc_w1)
{
    int blk = blockIdx.x;
    if (blk == 40) {
        if (threadIdx.x == 0) g_count = 0;
        if (threadIdx.x < Bb) g_bar[threadIdx.x] = 0;
        return;
    }

    const float *A, *W, *bias; float* C; int M, m0, n0;
    if (blk < 32) {
        A = img_fc_w; W = edge_fc_w1 + 256*256; bias = nullptr; C = g_Wc;
        M = 256; m0 = (blk >> 2) * 32; n0 = (blk & 3) * 64;
    } else if (blk < 36) {
        A = feat_img_2; W = img_fc_w; bias = img_fc_b; C = g_fi2v;
        M = Bb; m0 = 0; n0 = (blk - 32) * 64;
    } else {
        A = feat_img_ssl; W = img_fc_w; bias = img_fc_b; C = g_fsslv;
        M = Bb; m0 = 0; n0 = (blk - 36) * 64;
    }
    dev_gemm(A, W, bias, C, M, 256, m0, n0);
}

// ============================================================
// L2: mega1 — compact (256 blocks, full 65536 rows) || biask  [R13 verbatim]
// ============================================================
__global__ __launch_bounds__(256) void mega1_kernel(
    const int* __restrict__ mask, float* __restrict__ out,
    const float* __restrict__ b1, const float* __restrict__ bimg,
    const float* __restrict__ w1)
{
    int blk = blockIdx.x;
    if (blk < 256) {
        int r = blk * 256 + threadIdx.x;
        float4 z = make_float4(0.f, 0.f, 0.f, 0.f);
        float4* o = (float4*)(out + (size_t)r * 8);
        o[0] = z; o[1] = z;
        bool act = (mask[r] != 0);
        unsigned bal = __ballot_sync(0xffffffffu, act);
        if ((threadIdx.x & 31) == 0) g_maskb[r >> 5] = bal;
        if (act) {
            int p = atomicAdd(&g_count, 1);
            g_rows[p] = r;
        }
    } else {
        int b  = (blk - 256) >> 2;
        int ny = (blk - 256) & 3;
        int n = ny*64 + (threadIdx.x & 63);
        int part = threadIdx.x >> 6;
        __shared__ float red[4][64];
        const float* f2 = g_fi2v  + b*256;
        const float* f3 = g_fsslv + b*256;
        float s = 0.f;
        for (int h = part; h < 256; h += 4) {
            s += bimg[h] * __ldg(&w1[(256+h)*256 + n]);
            s += f2[h]   * __ldg(&w1[(512+h)*256 + n]);
            s += f3[h]   * __ldg(&w1[(768+h)*256 + n]);
        }
        red[part][threadIdx.x & 63] = s;
        __syncthreads();
        if (part == 0) {
            int l = threadIdx.x & 63;
            g_biasb[b*256 + n] = b1[n] + red[0][l] + red[1][l] + red[2][l] + red[3][l];
        }
    }
}

// ============================================================
// L3: scan_all — persistent prop0 + 5 scan steps  [R13 verbatim — validated]
// ============================================================
__global__ __launch_bounds__(256) void scan_all_kernel(
    const float* __restrict__ feat_body,
    const float* __restrict__ img_fc_w, const float* __restrict__ img_fc_b,
    const float* __restrict__ node_fc_w, const float* __restrict__ node_fc_b)
{
    __shared__ __align__(16) float AS[2][64][36];
    __shared__ __align__(16) float BS[2][32][36];
    __shared__ float msgT[32][65];
    __shared__ unsigned smask[128];

    int b  = blockIdx.x;
    int n0 = blockIdx.y * 32;
    int tid = threadIdx.x;
    if (tid < 128) smask[tid] = g_maskb[b*128 + tid];
    int tx = tid & 15, ty = tid >> 4;

    for (int phase = 0; phase < 6; phase++) {
        const float* Ab   = (phase == 0) ? (feat_body + (size_t)b*64*256)
                                         : (g_prop    + (size_t)b*64*256);
        const float* W    = (phase == 0) ? img_fc_w
                                         : (node_fc_w + (size_t)(phase-1)*65536);
        const float* bias = (phase == 0) ? img_fc_b
                                         : (node_fc_b + (phase-1)*256);

        auto issue = [&](int s, int k0) {
            #pragma unroll
            for (int p = 0; p < 2; p++) {
                int cid = p*256 + tid; int rr = cid >> 3, cc = cid & 7;
                cpa16cg(sptr(&AS[s][rr][cc*4]), Ab + (size_t)rr*256 + k0 + cc*4);
            }
            int rr2 = tid >> 3, cc2 = tid & 7;
            cpa16(sptr(&BS[s][rr2][cc2*4]), W + (size_t)(k0 + rr2)*256 + n0 + cc2*4, 16);
            CP_COMMIT();
        };

        ull acc[4] = {};
        issue(0, 0);
        for (int kt = 0; kt < 8; kt++) {
            if (kt + 1 < 8) { issue((kt+1)&1, (kt+1)*32); cp_wait<1>(); }
            else            { cp_wait<0>(); }
            __syncthreads();
            int s = kt & 1;
            #pragma unroll
            for (int k = 0; k < 32; k++) {
                float2 bv = *(float2*)&BS[s][k][tx*2];
                ull bp = pack2(bv.x, bv.y);
                #pragma unroll
                for (int q = 0; q < 4; q++) {
                    float a = AS[s][ty*4+q][k];
                    fma2(acc[q], pack2(a, a), bp);
                }
            }
            __syncthreads();
        }

        float b0 = bias[n0 + tx*2], b1 = bias[n0 + tx*2 + 1];
        if (phase == 0) {
            float* pr = g_prop + (size_t)b*64*256;
            #pragma unroll
            for (int q = 0; q < 4; q++) {
                int row = ty*4 + q;
                float v0, v1;
                unpack2(acc[q], v0, v1);
                *(float2*)&pr[(size_t)row*256 + n0 + tx*2] =
                    make_float2(v0 + b0, v1 + b1);
            }
        } else {
            int t = phase - 1;
            float* msgg = g_msg + ((size_t)t*Bb + b) * 64 * 256;
            #pragma unroll
            for (int q = 0; q < 4; q++) {
                int row = ty*4 + q;
                float v0, v1;
                unpack2(acc[q], v0, v1);
                v0 += b0; v1 += b1;
                msgT[tx*2    ][row] = v0;
                msgT[tx*2 + 1][row] = v1;
                *(float2*)&msgg[(size_t)row*256 + n0 + tx*2] = make_float2(v0, v1);
            }
            __syncthreads();

            if (t < Tt - 1) {
                int i = tid >> 2, hg = tid & 3;
                float mi[8], av[8];
                #pragma unroll
                for (int hh = 0; hh < 8; hh++) { mi[hh] = msgT[hg*8+hh][i]; av[hh] = 0.f; }
                unsigned w0 = smask[i*2], w1m = smask[i*2 + 1];
                #pragma unroll 4
                for (int j = 0; j < 32; j++) {
                    if ((w0 >> j) & 1) {
                        #pragma unroll
                        for (int hh = 0; hh < 8; hh++) {
                            float mj = msgT[hg*8+hh][j];
                            av[hh] += fmaxf(mi[hh] + mj, 0.f) * mj;
                        }
                    }
                }
                #pragma unroll 4
                for (int j = 0; j < 32; j++) {
                    if ((w1m >> j) & 1) {
                        #pragma unroll
                        for (int hh = 0; hh < 8; hh++) {
                            float mj = msgT[hg*8+hh][j + 32];
                            av[hh] += fmaxf(mi[hh] + mj, 0.f) * mj;
                        }
                    }
                }
                float* pr = g_prop + ((size_t)b*64 + i)*256 + n0 + hg*8;
                #pragma unroll
                for (int hh = 0; hh < 8; hh++)
                    pr[hh] += fmaxf(mi[hh] + av[hh], 0.f);
            }
        }

        if (phase < 5) {
            __threadfence();
            __syncthreads();
            if (tid == 0) {
                atomicAdd(&g_bar[b], 1);
                while (atomicAdd(&g_bar[b], 0) < 8*(phase+1)) { }
            }
            __syncthreads();
        }
    }
}

// ============================================================
// L4: fuse_v7 — 2D warp tiling (2M x 4N warps), BM=64, BN=256, BK=32.
// Warp tile 32x64; thread tile 8x8 via (lane>>3, lane&7).
// Per k per thread: 4 x LDS.128 (A pair + B pair) for 64 MACs ->
// smem port ~48 cyc/k/CTA vs 128 FMA cyc/k/CTA: FMA-bound.
// smem: Bs 33.8K (reused as Hs) + As 9.2K (reused as w2s) + idx 1K ≈ 44K.
// ============================================================
__global__ __launch_bounds__(256) void fuse_kernel(
    const float* __restrict__ fimg1, const float* __restrict__ w1,
    const float* __restrict__ w2,    const float* __restrict__ b2,
    float* __restrict__ out)
{
    __shared__ __align__(16) float Bs[32][264];  // [k][n]; reused as Hs[32][264]
    __shared__ __align__(16) float As[32][72];   // [k][row]; reused as w2s[2304]
    __shared__ int sRow[64], sB[64], sBI[64], sBJ[64];

    int cnt = g_count;
    int m0  = blockIdx.x * 64;
    if (m0 >= cnt) return;
    int tid = threadIdx.x;

    if (tid < 64) {
        int cl  = min(m0 + tid, cnt - 1);
        int row = g_rows[cl];
        int b = row >> 12, i = (row >> 6) & 63, j = row & 63;
        sRow[tid] = row;
        sB[tid]   = b;
        sBI[tid]  = (b*64 + i) * 256;
        sBJ[tid]  = (b*64 + j) * 256;
    }
    __syncthreads();

    int lane = tid & 31, wid = tid >> 5;
    int wm = wid & 1, wn = wid >> 1;    // 2 M-warps x 4 N-warps
    int r2 = lane >> 3, c2 = lane & 7;  // 4 row-groups x 8 col-groups
    int arow = wm*32 + r2*8;            // thread rows arow..arow+7
    int bcol = wn*64 + c2*8;            // thread cols bcol..bcol+7

    ull acc[8][4];
    #pragma unroll
    for (int q = 0; q < 8; q++)
        #pragma unroll
        for (int c = 0; c < 4; c++) acc[q][c] = 0ULL;

    for (int k0 = 0; k0 < 512; k0 += 32) {
        const float* Bsrc = (k0 < 256) ? (w1 + (size_t)k0*256)
                                       : (g_Wc + (size_t)(k0-256)*256);
        #pragma unroll
        for (int p = 0; p < 8; p++) {
            int c = p*256 + tid; int kk = c >> 6, c4 = c & 63;
            *(float4*)&Bs[kk][c4*4] = *(const float4*)&Bsrc[(size_t)kk*256 + c4*4];
        }
        if (k0 < 256) {
            #pragma unroll
            for (int p = 0; p < 8; p++) {
                int lin = p*256 + tid; int r = lin >> 5, kk = lin & 31;
                int k = k0 + kk;
                const float* mi = g_msg + sBI[r] + k;
                const float* mj = g_msg + sBJ[r] + k;
                float m = mi[0] + mj[0];
                #pragma unroll
                for (int t = 1; t < Tt; t++)
                    m = fmaxf(m, mi[(size_t)t*BNH] + mj[(size_t)t*BNH]);
                As[kk][r] = fmaxf(m, 0.f);
            }
        } else {
            #pragma unroll
            for (int p = 0; p < 8; p++) {
                int lin = p*256 + tid; int r = lin >> 5, kk = lin & 31;
                As[kk][r] = __ldg(&fimg1[(size_t)sRow[r]*256 + (k0-256) + kk]);
            }
        }
        __syncthreads();
        #pragma unroll
        for (int k = 0; k < 32; k++) {
            float4 a0 = *(float4*)&As[k][arow];
            float4 a1 = *(float4*)&As[k][arow + 4];
            float4 b0 = *(float4*)&Bs[k][bcol];
            float4 b1 = *(float4*)&Bs[k][bcol + 4];
            ull bp0 = pack2(b0.x,b0.y), bp1 = pack2(b0.z,b0.w);
            ull bp2 = pack2(b1.x,b1.y), bp3 = pack2(b1.z,b1.w);
            float av[8] = {a0.x,a0.y,a0.z,a0.w,a1.x,a1.y,a1.z,a1.w};
            #pragma unroll
            for (int q = 0; q < 8; q++) {
                ull aa = pack2(av[q], av[q]);
                fma2(acc[q][0], aa, bp0); fma2(acc[q][1], aa, bp1);
                fma2(acc[q][2], aa, bp2); fma2(acc[q][3], aa, bp3);
            }
        }
        __syncthreads();
    }

    // A tile dead: alias its smem as w2s (256*9 floats = 9216 B).
    float* w2s = &As[0][0];
    for (int idx = tid; idx < 2048; idx += 256) {
        int h = idx >> 3, e = idx & 7;
        w2s[h*9 + e] = __ldg(&w2[idx]);
    }

    // Epilogue in two 32-row halves (by wm); hidden lives in Bs (as Hs).
    float (*Hs)[264] = (float(*)[264])Bs;
    #pragma unroll
    for (int half = 0; half < 2; half++) {
        if (wm == half) {
            #pragma unroll
            for (int q = 0; q < 8; q++) {
                int rl = r2*8 + q;                 // local row 0..31
                const float* bb = g_biasb + sB[half*32 + rl]*256;
                float h[8];
                unpack2(acc[q][0], h[0], h[1]);
                unpack2(acc[q][1], h[2], h[3]);
                unpack2(acc[q][2], h[4], h[5]);
                unpack2(acc[q][3], h[6], h[7]);
                #pragma unroll
                for (int c = 0; c < 8; c++) {
                    int col = bcol + c;
                    Hs[rl][col] = fmaxf(h[c] + __ldg(&bb[col]), 0.f);
                }
            }
        }
        __syncthreads();
        int rl = tid >> 3, e = tid & 7;
        int gidx = m0 + half*32 + rl;
        if (gidx < cnt) {
            float s = 0.f;
            const float* hrow = Hs[rl];
            #pragma unroll 8
            for (int h = 0; h < 256; h++) s += hrow[h] * w2s[h*9 + e];
            out[(size_t)sRow[half*32 + rl]*8 + e] = s + __ldg(&b2[e]);
        }
        __syncthreads();
    }
}

// ============================================================
extern "C" void kernel_launch(void* const* d_in, const int* in_sizes, int n_in,
                              void* d_out, int out_size)
{
    const float* feat_body    = (const float*)d_in[0];
    const float* feat_img_1   = (const float*)d_in[1];
    const float* feat_img_2   = (const float*)d_in[2];
    const float* feat_img_ssl = (const float*)d_in[3];
    const int*   full_mask    = (const int*)  d_in[4];
    const float* img_fc_w     = (const float*)d_in[5];
    const float* img_fc_b     = (const float*)d_in[6];
    const float* node_fc_w    = (const float*)d_in[7];
    const float* node_fc_b    = (const float*)d_in[8];
    const float* edge_fc_w1   = (const float*)d_in[9];
    const float* edge_fc_b1   = (const float*)d_in[10];
    const float* edge_fc_w2   = (const float*)d_in[11];
    const float* edge_fc_b2   = (const float*)d_in[12];
    float* out = (float*)d_out;

    // L1: Wc || fi2v || fsslv || zero(g_count, g_bar)
    mega0_kernel<<<41, 256>>>(img_fc_w, img_fc_b,
                              feat_img_2, feat_img_ssl, edge_fc_w1);
    // L2: compact (full 65536 rows) || biask
    mega1_kernel<<<320, 256>>>(full_mask, out, edge_fc_b1, img_fc_b, edge_fc_w1);
    // L3: persistent scan (prop0 + 5 steps, per-batch barriers)
    scan_all_kernel<<<dim3(Bb, 8), 256>>>(feat_body, img_fc_w, img_fc_b,
                                          node_fc_w, node_fc_b);
    // L4: 2D-warp-tiled fuse
    fuse_kernel<<<ROWS/64, 256>>>(feat_img_1, edge_fc_w1, edge_fc_w2,
                                  edge_fc_b2, out);
}

// round 17
// speedup vs baseline: 1.5620x; 1.3045x over previous
#include <cuda_runtime.h>
#include <cstdint>

#define Bb 16
#define Nn 64
#define Hh 256
#define Tt 5
#define ROWS (Bb*Nn*Nn)      // 65536 (b,i,j) rows
#define BNH  (Bb*Nn*Hh)      // 262144

typedef unsigned long long ull;

// ---- device scratch ----
__device__ float g_prop [BNH];
__device__ float g_msg  [Tt*BNH];
__device__ float g_Wc   [Hh*Hh];
__device__ float g_fi2v [Bb*Hh];
__device__ float g_fsslv[Bb*Hh];
__device__ float g_biasb[Bb*Hh];
__device__ int   g_rows [ROWS];
__device__ unsigned g_maskb[ROWS/32];   // 2048 words
__device__ int   g_count;
__device__ int   g_bar[Bb];

// ---- packed f32x2 helpers ----
__device__ __forceinline__ ull pack2(float lo, float hi) {
    ull r; asm("mov.b64 %0, {%1,%2};" : "=l"(r) : "f"(lo), "f"(hi)); return r;
}
__device__ __forceinline__ void fma2(ull& d, ull a, ull b) {
    asm("fma.rn.f32x2 %0, %1, %2, %0;" : "+l"(d) : "l"(a), "l"(b));
}
__device__ __forceinline__ void unpack2(ull v, float& lo, float& hi) {
    asm("mov.b64 {%0,%1}, %2;" : "=f"(lo), "=f"(hi) : "l"(v));
}

// ---- cp.async helpers ----
__device__ __forceinline__ uint32_t sptr(const void* p) {
    return (uint32_t)__cvta_generic_to_shared(p);
}
__device__ __forceinline__ void cpa16(uint32_t dst, const void* src, int szbytes) {
    asm volatile("cp.async.ca.shared.global [%0], [%1], 16, %2;"
                 :: "r"(dst), "l"(src), "r"(szbytes));
}
__device__ __forceinline__ void cpa16cg(uint32_t dst, const void* src) {
    asm volatile("cp.async.cg.shared.global [%0], [%1], 16;"
                 :: "r"(dst), "l"(src));
}
#define CP_COMMIT() asm volatile("cp.async.commit_group;")
template<int N> __device__ __forceinline__ void cp_wait() {
    asm volatile("cp.async.wait_group %0;" :: "n"(N));
}

// ============================================================
// Device GEMM body [validated]
// ============================================================
__device__ void dev_gemm(
    const float* __restrict__ A, const float* __restrict__ W,
    const float* __restrict__ bias, float* __restrict__ C,
    int M, int K, int m0, int n0)
{
    __shared__ __align__(16) float AS[2][32][36];
    __shared__ __align__(16) float BS[2][32][64];
    int tid = threadIdx.x;

    int ar = tid >> 3, ac = tid & 7;
    int bk0 = tid >> 4, bc0 = tid & 15;

    auto issue = [&](int s, int k0) {
        bool aok = (m0 + ar) < M;
        const float* asrc = A + (size_t)(aok ? (m0 + ar) : 0) * K + k0 + ac*4;
        cpa16(sptr(&AS[s][ar][ac*4]), asrc, aok ? 16 : 0);
        #pragma unroll
        for (int q = 0; q < 2; q++) {
            int kk = bk0 + q*16;
            cpa16(sptr(&BS[s][kk][bc0*4]), W + (size_t)(k0+kk)*256 + n0 + bc0*4, 16);
        }
        CP_COMMIT();
    };

    int tx = tid & 15, ty = tid >> 4;
    ull acc[2][2] = {};

    issue(0, 0);
    int nt = K >> 5;
    for (int t = 0; t < nt; t++) {
        if (t + 1 < nt) { issue((t+1)&1, (t+1)*32); cp_wait<1>(); }
        else            { cp_wait<0>(); }
        __syncthreads();
        int s = t & 1;
        #pragma unroll
        for (int k = 0; k < 32; k++) {
            float a0 = AS[s][ty*2+0][k];
            float a1 = AS[s][ty*2+1][k];
            float4 b = *(float4*)&BS[s][k][tx*4];
            ull bp0 = pack2(b.x, b.y), bp1 = pack2(b.z, b.w);
            ull aa0 = pack2(a0, a0),   aa1 = pack2(a1, a1);
            fma2(acc[0][0], aa0, bp0); fma2(acc[0][1], aa0, bp1);
            fma2(acc[1][0], aa1, bp0); fma2(acc[1][1], aa1, bp1);
        }
        __syncthreads();
    }

    #pragma unroll
    for (int q = 0; q < 2; q++) {
        int gr = m0 + ty*2 + q;
        if (gr < M) {
            float v[4];
            unpack2(acc[q][0], v[0], v[1]);
            unpack2(acc[q][1], v[2], v[3]);
            #pragma unroll
            for (int c = 0; c < 4; c++) {
                int gc = n0 + tx*4 + c;
                float o = v[c];
                if (bias) o += bias[gc];
                C[(size_t)gr*256 + gc] = o;
            }
        }
    }
}

// ============================================================
// L1: mega0 — Wc || fi2v || fsslv || zero(g_count, g_bar)  [R13 verbatim]
// ============================================================
__global__ __launch_bounds__(256) void mega0_kernel(
    const float* __restrict__ img_fc_w, const float* __restrict__ img_fc_b,
    const float* __restrict__ feat_img_2, const float* __restrict__ feat_img_ssl,
    const float* __restrict__ edge_fc_w1)
{
    int blk = blockIdx.x;
    if (blk == 40) {
        if (threadIdx.x == 0) g_count = 0;
        if (threadIdx.x < Bb) g_bar[threadIdx.x] = 0;
        return;
    }

    const float *A, *W, *bias; float* C; int M, m0, n0;
    if (blk < 32) {
        A = img_fc_w; W = edge_fc_w1 + 256*256; bias = nullptr; C = g_Wc;
        M = 256; m0 = (blk >> 2) * 32; n0 = (blk & 3) * 64;
    } else if (blk < 36) {
        A = feat_img_2; W = img_fc_w; bias = img_fc_b; C = g_fi2v;
        M = Bb; m0 = 0; n0 = (blk - 32) * 64;
    } else {
        A = feat_img_ssl; W = img_fc_w; bias = img_fc_b; C = g_fsslv;
        M = Bb; m0 = 0; n0 = (blk - 36) * 64;
    }
    dev_gemm(A, W, bias, C, M, 256, m0, n0);
}

// ============================================================
// L2: mega1 — compact (256 blocks, full 65536 rows) || biask  [R13 verbatim]
// ============================================================
__global__ __launch_bounds__(256) void mega1_kernel(
    const int* __restrict__ mask, float* __restrict__ out,
    const float* __restrict__ b1, const float* __restrict__ bimg,
    const float* __restrict__ w1)
{
    int blk = blockIdx.x;
    if (blk < 256) {
        int r = blk * 256 + threadIdx.x;
        float4 z = make_float4(0.f, 0.f, 0.f, 0.f);
        float4* o = (float4*)(out + (size_t)r * 8);
        o[0] = z; o[1] = z;
        bool act = (mask[r] != 0);
        unsigned bal = __ballot_sync(0xffffffffu, act);
        if ((threadIdx.x & 31) == 0) g_maskb[r >> 5] = bal;
        if (act) {
            int p = atomicAdd(&g_count, 1);
            g_rows[p] = r;
        }
    } else {
        int b  = (blk - 256) >> 2;
        int ny = (blk - 256) & 3;
        int n = ny*64 + (threadIdx.x & 63);
        int part = threadIdx.x >> 6;
        __shared__ float red[4][64];
        const float* f2 = g_fi2v  + b*256;
        const float* f3 = g_fsslv + b*256;
        float s = 0.f;
        for (int h = part; h < 256; h += 4) {
            s += bimg[h] * __ldg(&w1[(256+h)*256 + n]);
            s += f2[h]   * __ldg(&w1[(512+h)*256 + n]);
            s += f3[h]   * __ldg(&w1[(768+h)*256 + n]);
        }
        red[part][threadIdx.x & 63] = s;
        __syncthreads();
        if (part == 0) {
            int l = threadIdx.x & 63;
            g_biasb[b*256 + n] = b1[n] + red[0][l] + red[1][l] + red[2][l] + red[3][l];
        }
    }
}

// ============================================================
// L3: scan_all — persistent prop0 + 5 scan steps  [R13 verbatim — validated]
// ============================================================
__global__ __launch_bounds__(256) void scan_all_kernel(
    const float* __restrict__ feat_body,
    const float* __restrict__ img_fc_w, const float* __restrict__ img_fc_b,
    const float* __restrict__ node_fc_w, const float* __restrict__ node_fc_b)
{
    __shared__ __align__(16) float AS[2][64][36];
    __shared__ __align__(16) float BS[2][32][36];
    __shared__ float msgT[32][65];
    __shared__ unsigned smask[128];

    int b  = blockIdx.x;
    int n0 = blockIdx.y * 32;
    int tid = threadIdx.x;
    if (tid < 128) smask[tid] = g_maskb[b*128 + tid];
    int tx = tid & 15, ty = tid >> 4;

    for (int phase = 0; phase < 6; phase++) {
        const float* Ab   = (phase == 0) ? (feat_body + (size_t)b*64*256)
                                         : (g_prop    + (size_t)b*64*256);
        const float* W    = (phase == 0) ? img_fc_w
                                         : (node_fc_w + (size_t)(phase-1)*65536);
        const float* bias = (phase == 0) ? img_fc_b
                                         : (node_fc_b + (phase-1)*256);

        auto issue = [&](int s, int k0) {
            #pragma unroll
            for (int p = 0; p < 2; p++) {
                int cid = p*256 + tid; int rr = cid >> 3, cc = cid & 7;
                cpa16cg(sptr(&AS[s][rr][cc*4]), Ab + (size_t)rr*256 + k0 + cc*4);
            }
            int rr2 = tid >> 3, cc2 = tid & 7;
            cpa16(sptr(&BS[s][rr2][cc2*4]), W + (size_t)(k0 + rr2)*256 + n0 + cc2*4, 16);
            CP_COMMIT();
        };

        ull acc[4] = {};
        issue(0, 0);
        for (int kt = 0; kt < 8; kt++) {
            if (kt + 1 < 8) { issue((kt+1)&1, (kt+1)*32); cp_wait<1>(); }
            else            { cp_wait<0>(); }
            __syncthreads();
            int s = kt & 1;
            #pragma unroll
            for (int k = 0; k < 32; k++) {
                float2 bv = *(float2*)&BS[s][k][tx*2];
                ull bp = pack2(bv.x, bv.y);
                #pragma unroll
                for (int q = 0; q < 4; q++) {
                    float a = AS[s][ty*4+q][k];
                    fma2(acc[q], pack2(a, a), bp);
                }
            }
            __syncthreads();
        }

        float b0 = bias[n0 + tx*2], b1 = bias[n0 + tx*2 + 1];
        if (phase == 0) {
            float* pr = g_prop + (size_t)b*64*256;
            #pragma unroll
            for (int q = 0; q < 4; q++) {
                int row = ty*4 + q;
                float v0, v1;
                unpack2(acc[q], v0, v1);
                *(float2*)&pr[(size_t)row*256 + n0 + tx*2] =
                    make_float2(v0 + b0, v1 + b1);
            }
        } else {
            int t = phase - 1;
            float* msgg = g_msg + ((size_t)t*Bb + b) * 64 * 256;
            #pragma unroll
            for (int q = 0; q < 4; q++) {
                int row = ty*4 + q;
                float v0, v1;
                unpack2(acc[q], v0, v1);
                v0 += b0; v1 += b1;
                msgT[tx*2    ][row] = v0;
                msgT[tx*2 + 1][row] = v1;
                *(float2*)&msgg[(size_t)row*256 + n0 + tx*2] = make_float2(v0, v1);
            }
            __syncthreads();

            if (t < Tt - 1) {
                int i = tid >> 2, hg = tid & 3;
                float mi[8], av[8];
                #pragma unroll
                for (int hh = 0; hh < 8; hh++) { mi[hh] = msgT[hg*8+hh][i]; av[hh] = 0.f; }
                unsigned w0 = smask[i*2], w1m = smask[i*2 + 1];
                #pragma unroll 4
                for (int j = 0; j < 32; j++) {
                    if ((w0 >> j) & 1) {
                        #pragma unroll
                        for (int hh = 0; hh < 8; hh++) {
                            float mj = msgT[hg*8+hh][j];
                            av[hh] += fmaxf(mi[hh] + mj, 0.f) * mj;
                        }
                    }
                }
                #pragma unroll 4
                for (int j = 0; j < 32; j++) {
                    if ((w1m >> j) & 1) {
                        #pragma unroll
                        for (int hh = 0; hh < 8; hh++) {
                            float mj = msgT[hg*8+hh][j + 32];
                            av[hh] += fmaxf(mi[hh] + mj, 0.f) * mj;
                        }
                    }
                }
                float* pr = g_prop + ((size_t)b*64 + i)*256 + n0 + hg*8;
                #pragma unroll
                for (int hh = 0; hh < 8; hh++)
                    pr[hh] += fmaxf(mi[hh] + av[hh], 0.f);
            }
        }

        if (phase < 5) {
            __threadfence();
            __syncthreads();
            if (tid == 0) {
                atomicAdd(&g_bar[b], 1);
                while (atomicAdd(&g_bar[b], 0) < 8*(phase+1)) { }
            }
            __syncthreads();
        }
    }
}

// ============================================================
// L4: fuse_v8 — 512 threads, 16 warps (2M x 8N), warp tile 32x32,
// thread tile 8x4 (acc = 16 ull = 32 regs) -> ~70 regs, 4 warps/SMSP.
// BM=64, BN=256, BK=32. Port: ~3 LDS.128/thread/k. Latency covered by
// 4 warps/SMSP (vs 2 in v7).
// smem: Bs 33.8K (reused as Hs) + As 9.2K (reused as w2s) + idx 1K ≈ 44K.
// ============================================================
__global__ __launch_bounds__(512) void fuse_kernel(
    const float* __restrict__ fimg1, const float* __restrict__ w1,
    const float* __restrict__ w2,    const float* __restrict__ b2,
    float* __restrict__ out)
{
    __shared__ __align__(16) float Bs[32][264];  // [k][n]; reused as Hs[32][264]
    __shared__ __align__(16) float As[32][72];   // [k][row]; reused as w2s[2304]
    __shared__ int sRow[64], sB[64], sBI[64], sBJ[64];

    int cnt = g_count;
    int m0  = blockIdx.x * 64;
    if (m0 >= cnt) return;
    int tid = threadIdx.x;

    if (tid < 64) {
        int cl  = min(m0 + tid, cnt - 1);
        int row = g_rows[cl];
        int b = row >> 12, i = (row >> 6) & 63, j = row & 63;
        sRow[tid] = row;
        sB[tid]   = b;
        sBI[tid]  = (b*64 + i) * 256;
        sBJ[tid]  = (b*64 + j) * 256;
    }
    __syncthreads();

    int lane = tid & 31, wid = tid >> 5;
    int wm = wid & 1, wn = wid >> 1;    // 2 M-warps x 8 N-warps
    int r2 = lane >> 3, c2 = lane & 7;  // 4 row-groups(8) x 8 col-groups(4)
    int arow = wm*32 + r2*8;            // thread rows arow..arow+7
    int bcol = wn*32 + c2*4;            // thread cols bcol..bcol+3

    ull acc[8][2];
    #pragma unroll
    for (int q = 0; q < 8; q++) { acc[q][0] = 0ULL; acc[q][1] = 0ULL; }

    for (int k0 = 0; k0 < 512; k0 += 32) {
        const float* Bsrc = (k0 < 256) ? (w1 + (size_t)k0*256)
                                       : (g_Wc + (size_t)(k0-256)*256);
        #pragma unroll
        for (int p = 0; p < 4; p++) {
            int c = p*512 + tid; int kk = c >> 6, c4 = c & 63;
            *(float4*)&Bs[kk][c4*4] = *(const float4*)&Bsrc[(size_t)kk*256 + c4*4];
        }
        if (k0 < 256) {
            #pragma unroll
            for (int p = 0; p < 4; p++) {
                int lin = p*512 + tid; int r = lin >> 5, kk = lin & 31;
                int k = k0 + kk;
                const float* mi = g_msg + sBI[r] + k;
                const float* mj = g_msg + sBJ[r] + k;
                float m = mi[0] + mj[0];
                #pragma unroll
                for (int t = 1; t < Tt; t++)
                    m = fmaxf(m, mi[(size_t)t*BNH] + mj[(size_t)t*BNH]);
                As[kk][r] = fmaxf(m, 0.f);
            }
        } else {
            #pragma unroll
            for (int p = 0; p < 4; p++) {
                int lin = p*512 + tid; int r = lin >> 5, kk = lin & 31;
                As[kk][r] = __ldg(&fimg1[(size_t)sRow[r]*256 + (k0-256) + kk]);
            }
        }
        __syncthreads();
        #pragma unroll
        for (int k = 0; k < 32; k++) {
            float4 a0 = *(float4*)&As[k][arow];
            float4 a1 = *(float4*)&As[k][arow + 4];
            float4 b0 = *(float4*)&Bs[k][bcol];
            ull bp0 = pack2(b0.x,b0.y), bp1 = pack2(b0.z,b0.w);
            float av[8] = {a0.x,a0.y,a0.z,a0.w,a1.x,a1.y,a1.z,a1.w};
            #pragma unroll
            for (int q = 0; q < 8; q++) {
                ull aa = pack2(av[q], av[q]);
                fma2(acc[q][0], aa, bp0); fma2(acc[q][1], aa, bp1);
            }
        }
        __syncthreads();
    }

    // A tile dead: alias its smem as w2s (256*9 floats = 9216 B).
    float* w2s = &As[0][0];
    for (int idx = tid; idx < 2048; idx += 512) {
        int h = idx >> 3, e = idx & 7;
        w2s[h*9 + e] = __ldg(&w2[idx]);
    }

    // Epilogue in two 32-row halves (by wm); hidden lives in Bs (as Hs).
    float (*Hs)[264] = (float(*)[264])Bs;
    #pragma unroll
    for (int half = 0; half < 2; half++) {
        if (wm == half) {
            #pragma unroll
            for (int q = 0; q < 8; q++) {
                int rl = r2*8 + q;                 // local row 0..31
                const float* bb = g_biasb + sB[half*32 + rl]*256;
                float h[4];
                unpack2(acc[q][0], h[0], h[1]);
                unpack2(acc[q][1], h[2], h[3]);
                #pragma unroll
                for (int c = 0; c < 4; c++) {
                    int col = bcol + c;
                    Hs[rl][col] = fmaxf(h[c] + __ldg(&bb[col]), 0.f);
                }
            }
        }
        __syncthreads();
        if (tid < 256) {
            int rl = tid >> 3, e = tid & 7;
            int gidx = m0 + half*32 + rl;
            if (gidx < cnt) {
                float s = 0.f;
                const float* hrow = Hs[rl];
                #pragma unroll 8
                for (int h = 0; h < 256; h++) s += hrow[h] * w2s[h*9 + e];
                out[(size_t)sRow[half*32 + rl]*8 + e] = s + __ldg(&b2[e]);
            }
        }
        __syncthreads();
    }
}

// ============================================================
extern "C" void kernel_launch(void* const* d_in, const int* in_sizes, int n_in,
                              void* d_out, int out_size)
{
    const float* feat_body    = (const float*)d_in[0];
    const float* feat_img_1   = (const float*)d_in[1];
    const float* feat_img_2   = (const float*)d_in[2];
    const float* feat_img_ssl = (const float*)d_in[3];
    const int*   full_mask    = (const int*)  d_in[4];
    const float* img_fc_w     = (const float*)d_in[5];
    const float* img_fc_b     = (const float*)d_in[6];
    const float* node_fc_w    = (const float*)d_in[7];
    const float* node_fc_b    = (const float*)d_in[8];
    const float* edge_fc_w1   = (const float*)d_in[9];
    const float* edge_fc_b1   = (const float*)d_in[10];
    const float* edge_fc_w2   = (const float*)d_in[11];
    const float* edge_fc_b2   = (const float*)d_in[12];
    float* out = (float*)d_out;

    // L1: Wc || fi2v || fsslv || zero(g_count, g_bar)
    mega0_kernel<<<41, 256>>>(img_fc_w, img_fc_b,
                              feat_img_2, feat_img_ssl, edge_fc_w1);
    // L2: compact (full 65536 rows) || biask
    mega1_kernel<<<320, 256>>>(full_mask, out, edge_fc_b1, img_fc_b, edge_fc_w1);
    // L3: persistent scan (prop0 + 5 steps, per-batch barriers)
    scan_all_kernel<<<dim3(Bb, 8), 256>>>(feat_body, img_fc_w, img_fc_b,
                                          node_fc_w, node_fc_b);
    // L4: 512-thread fuse (4 warps/SMSP latency cover)
    fuse_kernel<<<ROWS/64, 512>>>(feat_img_1, edge_fc_w1, edge_fc_w2,
                                  edge_fc_b2, out);
}